// round 13
// baseline (speedup 1.0000x reference)
#include <cuda_runtime.h>
#include <cuda_bf16.h>
#include <cuda_fp16.h>
#include <cstdint>

#define N_NODES 50000
#define N_PAD   50048              // 391 * 128
#define N_EDGES 25000
#define NNZ     800000
#define DIM     256

#define CH_E ((N_EDGES + 1023) / 1024)   // 25
#define CH_N ((N_NODES + 1023) / 1024)   // 49

// ---------------- scratch ----------------------------------------------------
__device__ __align__(16) __half g_Zh [N_NODES * DIM];     // fp16(X@W + b)  25.6MB
__device__ __align__(16) __half g_S2h[N_EDGES * DIM];     // fp16 step2     12.8MB
__device__ __align__(16) float  g_Wt [DIM * DIM];         // tf32-rounded W^T [n][k]
__device__ int   g_deg_v[N_NODES];
__device__ int   g_deg_e[N_EDGES];
__device__ float g_dv[N_NODES];
__device__ float g_de[N_EDGES];
__device__ int   g_off_e[N_EDGES + 1];
__device__ int   g_off_n[N_NODES + 1];
__device__ int   g_rank_v[NNZ];
__device__ int   g_rank_e[NNZ];
__device__ int   g_adj_e[NNZ];
__device__ int   g_adj_n[NNZ];
__device__ int   g_part_e[32];
__device__ int   g_part_n[64];
__device__ int   g_is64;

// ---------------- helpers ----------------------------------------------------
__device__ __forceinline__ int idx_at(const void* p, int i, int is64) {
    if (is64) return (int)(((const long long*)p)[i]);
    return ((const int*)p)[i];
}
__device__ __forceinline__ uint32_t f2tf32(float f) {
    uint32_t r;
    asm("cvt.rna.tf32.f32 %0, %1;" : "=r"(r) : "f"(f));
    return r;
}
__device__ __forceinline__ void mma_tf32(float* c, uint32_t a0, uint32_t a1,
                                         uint32_t a2, uint32_t a3,
                                         uint32_t b0, uint32_t b1) {
    asm volatile(
        "mma.sync.aligned.m16n8k8.row.col.f32.tf32.tf32.f32 "
        "{%0,%1,%2,%3}, {%4,%5,%6,%7}, {%8,%9}, {%0,%1,%2,%3};\n"
        : "+f"(c[0]), "+f"(c[1]), "+f"(c[2]), "+f"(c[3])
        : "r"(a0), "r"(a1), "r"(a2), "r"(a3), "r"(b0), "r"(b1));
}
// accumulate 8 fp16 lanes (one uint4) into float acc[8], scaled by s
__device__ __forceinline__ void acc8(float* a, uint4 v, float s) {
    __half2 h0 = *(__half2*)&v.x, h1 = *(__half2*)&v.y;
    __half2 h2 = *(__half2*)&v.z, h3 = *(__half2*)&v.w;
    float2 f0 = __half22float2(h0), f1 = __half22float2(h1);
    float2 f2 = __half22float2(h2), f3 = __half22float2(h3);
    a[0] = fmaf(f0.x, s, a[0]); a[1] = fmaf(f0.y, s, a[1]);
    a[2] = fmaf(f1.x, s, a[2]); a[3] = fmaf(f1.y, s, a[3]);
    a[4] = fmaf(f2.x, s, a[4]); a[5] = fmaf(f2.y, s, a[5]);
    a[6] = fmaf(f3.x, s, a[6]); a[7] = fmaf(f3.y, s, a[7]);
}
// pairwise: fp16 add two rows, convert once, fp32 accumulate
__device__ __forceinline__ void accp(float* a, uint4 va, uint4 vb) {
    __half2 s0 = __hadd2(*(__half2*)&va.x, *(__half2*)&vb.x);
    __half2 s1 = __hadd2(*(__half2*)&va.y, *(__half2*)&vb.y);
    __half2 s2 = __hadd2(*(__half2*)&va.z, *(__half2*)&vb.z);
    __half2 s3 = __hadd2(*(__half2*)&va.w, *(__half2*)&vb.w);
    float2 f0 = __half22float2(s0), f1 = __half22float2(s1);
    float2 f2 = __half22float2(s2), f3 = __half22float2(s3);
    a[0] += f0.x; a[1] += f0.y; a[2] += f1.x; a[3] += f1.y;
    a[4] += f2.x; a[5] += f2.y; a[6] += f3.x; a[7] += f3.y;
}

// ---------------- detect index dtype (32 threads, 64 qwords) -----------------
__global__ void detect_kernel(const void* node_idx) {
    const unsigned long long* q = (const unsigned long long*)node_idx;
    int t = threadIdx.x;
    int bad = ((q[t] >> 32) != 0ull) || ((q[t + 32] >> 32) != 0ull);
    bad = __any_sync(0xffffffffu, bad);
    if (t == 0) g_is64 = bad ? 0 : 1;
}

// ---------------- zero degree counters (off critical path) -------------------
__global__ void zero_kernel() {
    int i = blockIdx.x * blockDim.x + threadIdx.x;
    if (i < N_NODES) g_deg_v[i] = 0;
    if (i < N_EDGES) g_deg_e[i] = 0;
}

// ---------------- degree histogram + rank capture (split v/e) ----------------
__global__ void count_v_kernel(const void* ni) {
    int i = blockIdx.x * blockDim.x + threadIdx.x;
    if (i >= NNZ) return;
    int n = idx_at(ni, i, g_is64);
    g_rank_v[i] = atomicAdd(&g_deg_v[n], 1);
}
__global__ void count_e_kernel(const void* ei) {
    int i = blockIdx.x * blockDim.x + threadIdx.x;
    if (i >= NNZ) return;
    int e = idx_at(ei, i, g_is64);
    g_rank_e[i] = atomicAdd(&g_deg_e[e], 1);
}

// ---------------- convert W -> transposed tf32-rounded fp32 ------------------
__global__ void convert_w_kernel(const float* __restrict__ W) {
    int n = blockIdx.x;
    int k = threadIdx.x;
    float w = W[(size_t)k * DIM + n];
    g_Wt[n * DIM + k] = __uint_as_float(f2tf32(w));
}

// ---------------- GEMM (single-pass tf32 tensor cores, A-reg prefetch) -------
// Zh = fp16(X @ W + b).  128x128 tile, K-chunks of 32, 8 warps (2m x 4n).
#define SAF 36
__global__ __launch_bounds__(256, 2)
void gemm_tf32_kernel(const float* __restrict__ X,
                      const float* __restrict__ bias) {
    __shared__ __align__(16) float As[128][SAF];
    __shared__ __align__(16) float Bs[128][SAF];

    int t    = threadIdx.x;
    int warp = t >> 5, lane = t & 31;
    int wm = warp >> 2, wn = warp & 3;
    int g  = lane >> 2, q = lane & 3;
    int m0 = blockIdx.x * 128;
    int n0 = blockIdx.y * 128;

    float acc[4][4][4];
    #pragma unroll
    for (int i = 0; i < 4; i++)
        #pragma unroll
        for (int j = 0; j < 4; j++)
            #pragma unroll
            for (int r = 0; r < 4; r++) acc[i][j][r] = 0.0f;

    int lrow = t >> 1;        // 0..127
    int lseg = t & 1;         // 16-float segment
    int gr = m0 + lrow;

    // prefetch A chunk 0 into registers
    float vf[16];
    {
        if (gr < N_NODES) {
            const float4* src = (const float4*)&X[(size_t)gr * DIM + 0 + lseg * 16];
            float4 f0 = src[0], f1 = src[1], f2 = src[2], f3 = src[3];
            vf[0]=f0.x; vf[1]=f0.y; vf[2]=f0.z; vf[3]=f0.w;
            vf[4]=f1.x; vf[5]=f1.y; vf[6]=f1.z; vf[7]=f1.w;
            vf[8]=f2.x; vf[9]=f2.y; vf[10]=f2.z; vf[11]=f2.w;
            vf[12]=f3.x; vf[13]=f3.y; vf[14]=f3.z; vf[15]=f3.w;
        } else {
            #pragma unroll
            for (int k = 0; k < 16; k++) vf[k] = 0.0f;
        }
    }

    for (int k0 = 0; k0 < DIM; k0 += 32) {
        // A: tf32-round prefetched regs -> smem
        {
            uint32_t tv[16];
            #pragma unroll
            for (int k = 0; k < 16; k++) tv[k] = f2tf32(vf[k]);
            #pragma unroll
            for (int p = 0; p < 4; p++)
                *(uint4*)&As[lrow][lseg * 16 + p * 4] = ((uint4*)tv)[p];
        }
        // B: copy from L2-resident pre-rounded g_Wt
        {
            const float4* src = (const float4*)&g_Wt[(n0 + lrow) * DIM + k0 + lseg * 16];
            #pragma unroll
            for (int p = 0; p < 4; p++)
                *(float4*)&Bs[lrow][lseg * 16 + p * 4] = src[p];
        }
        __syncthreads();

        // prefetch NEXT A chunk while MMAs run on this one
        if (k0 + 32 < DIM) {
            if (gr < N_NODES) {
                const float4* src = (const float4*)&X[(size_t)gr * DIM + k0 + 32 + lseg * 16];
                float4 f0 = src[0], f1 = src[1], f2 = src[2], f3 = src[3];
                vf[0]=f0.x; vf[1]=f0.y; vf[2]=f0.z; vf[3]=f0.w;
                vf[4]=f1.x; vf[5]=f1.y; vf[6]=f1.z; vf[7]=f1.w;
                vf[8]=f2.x; vf[9]=f2.y; vf[10]=f2.z; vf[11]=f2.w;
                vf[12]=f3.x; vf[13]=f3.y; vf[14]=f3.z; vf[15]=f3.w;
            }
        }

        #pragma unroll
        for (int ksub = 0; ksub < 32; ksub += 8) {
            uint32_t b0[4], b1[4];
            #pragma unroll
            for (int j = 0; j < 4; j++) {
                int nr = wn * 32 + j * 8 + g;
                b0[j] = *(const uint32_t*)&Bs[nr][ksub + q];
                b1[j] = *(const uint32_t*)&Bs[nr][ksub + q + 4];
            }
            #pragma unroll
            for (int i = 0; i < 4; i++) {
                int mr = wm * 64 + i * 16;
                uint32_t a0 = *(const uint32_t*)&As[mr + g][ksub + q];
                uint32_t a1 = *(const uint32_t*)&As[mr + 8 + g][ksub + q];
                uint32_t a2 = *(const uint32_t*)&As[mr + g][ksub + q + 4];
                uint32_t a3 = *(const uint32_t*)&As[mr + 8 + g][ksub + q + 4];
                #pragma unroll
                for (int j = 0; j < 4; j++)
                    mma_tf32(acc[i][j], a0, a1, a2, a3, b0[j], b1[j]);
            }
        }
        __syncthreads();
    }

    // epilogue: + bias, store fp16 Zh
    #pragma unroll
    for (int j = 0; j < 4; j++) {
        int cb = n0 + wn * 32 + j * 8 + q * 2;
        float2 bb = *(const float2*)&bias[cb];
        #pragma unroll
        for (int i = 0; i < 4; i++) {
            int r = m0 + wm * 64 + i * 16 + g;
            if (r < N_NODES) {
                __half2 o = __floats2half2_rn(acc[i][j][0] + bb.x, acc[i][j][1] + bb.y);
                *(__half2*)&g_Zh[(size_t)r * DIM + cb] = o;
            }
            if (r + 8 < N_NODES) {
                __half2 o = __floats2half2_rn(acc[i][j][2] + bb.x, acc[i][j][3] + bb.y);
                *(__half2*)&g_Zh[(size_t)(r + 8) * DIM + cb] = o;
            }
        }
    }
}

// ---------------- scan phase 1 -----------------------------------------------
__global__ void scan_p1_kernel() {
    int which = blockIdx.y;
    int n          = which ? N_NODES : N_EDGES;
    const int* deg = which ? g_deg_v : g_deg_e;
    int*  off      = which ? g_off_n : g_off_e;
    float* dinv    = which ? g_dv    : g_de;
    int*  part     = which ? g_part_n : g_part_e;

    int base = blockIdx.x * 1024;
    if (base >= n) return;
    int tid = threadIdx.x;
    int i = base + tid;
    int v = (i < n) ? deg[i] : 0;

    int x = v;
    int lane = tid & 31, warp = tid >> 5;
    #pragma unroll
    for (int s = 1; s < 32; s <<= 1) {
        int t = __shfl_up_sync(0xffffffffu, x, s);
        if (lane >= s) x += t;
    }
    __shared__ int wsum[32];
    if (lane == 31) wsum[warp] = x;
    __syncthreads();
    if (warp == 0) {
        int y = wsum[lane];
        #pragma unroll
        for (int s = 1; s < 32; s <<= 1) {
            int t = __shfl_up_sync(0xffffffffu, y, s);
            if (lane >= s) y += t;
        }
        wsum[lane] = y;
    }
    __syncthreads();
    int incl = x + (warp ? wsum[warp - 1] : 0);
    if (i < n) {
        off[i] = incl - v;
        dinv[i] = (v > 0) ? (which ? rsqrtf((float)v) : 1.0f / (float)v) : 0.0f;
    }
    if (tid == 1023) part[blockIdx.x] = incl;
}

// ---------------- scan phase 2 -----------------------------------------------
__global__ void scan_p2_kernel() {
    __shared__ int pe[32], pn[64];
    int t = threadIdx.x;
    if (t < 32) pe[t] = (t < CH_E) ? g_part_e[t] : 0;
    if (t < 64) pn[t] = (t < CH_N) ? g_part_n[t] : 0;
    __syncthreads();
    #pragma unroll
    for (int s = 1; s < 64; s <<= 1) {
        int ve = (t < 32 && t >= s) ? pe[t - s] : 0;
        int vn = (t < 64 && t >= s) ? pn[t - s] : 0;
        __syncthreads();
        if (t < 32) pe[t] += ve;
        if (t < 64) pn[t] += vn;
        __syncthreads();
    }
    if (t < 32) g_part_e[t] = t ? pe[t - 1] : 0;
    if (t < 64) g_part_n[t] = t ? pn[t - 1] : 0;
    if (t == 0) { g_off_e[N_EDGES] = NNZ; g_off_n[N_NODES] = NNZ; }
}

// ---------------- scan phase 3 -----------------------------------------------
__global__ void scan_p3_kernel() {
    int which = blockIdx.y;
    int n    = which ? N_NODES : N_EDGES;
    int* off = which ? g_off_n : g_off_e;
    int i = blockIdx.x * 1024 + threadIdx.x;
    if (i < n) off[i] += (which ? g_part_n : g_part_e)[blockIdx.x];
}

// ---------------- CSR fill, edge side (atomic-free via ranks) ----------------
__global__ void fill_e_kernel(const void* ni, const void* ei) {
    int base = (blockIdx.x * blockDim.x + threadIdx.x) * 4;
    if (base >= NNZ) return;
    int is64 = g_is64;
    int n[4], e[4], r[4];
    #pragma unroll
    for (int u = 0; u < 4; u++) n[u] = idx_at(ni, base + u, is64);
    #pragma unroll
    for (int u = 0; u < 4; u++) e[u] = idx_at(ei, base + u, is64);
    #pragma unroll
    for (int u = 0; u < 4; u++) r[u] = g_rank_e[base + u];
    #pragma unroll
    for (int u = 0; u < 4; u++)
        g_adj_e[g_off_e[e[u]] + r[u]] = n[u];
}

// ---------------- CSR fill, node side (atomic-free via ranks) ----------------
__global__ void fill_n_kernel(const void* ni, const void* ei) {
    int base = (blockIdx.x * blockDim.x + threadIdx.x) * 4;
    if (base >= NNZ) return;
    int is64 = g_is64;
    int n[4], e[4], r[4];
    #pragma unroll
    for (int u = 0; u < 4; u++) n[u] = idx_at(ni, base + u, is64);
    #pragma unroll
    for (int u = 0; u < 4; u++) e[u] = idx_at(ei, base + u, is64);
    #pragma unroll
    for (int u = 0; u < 4; u++) r[u] = g_rank_v[base + u];
    #pragma unroll
    for (int u = 0; u < 4; u++)
        g_adj_n[g_off_n[n[u]] + r[u]] = e[u];
}

// ---------------- S2h[e] = fp16( d_e * sum_{n in e} d_v[n] * Zh[n] ) ---------
__global__ void edge_gather_kernel() {
    int w    = (blockIdx.x * blockDim.x + threadIdx.x) >> 5;
    int lane = threadIdx.x & 31;
    if (w >= N_EDGES) return;
    int s = g_off_e[w], e = g_off_e[w + 1];
    float a[8] = {0.f, 0.f, 0.f, 0.f, 0.f, 0.f, 0.f, 0.f};
    int j = s;
    int lim8 = s + ((e - s) & ~7);
    for (; j < lim8; j += 8) {
        int   n[8]; float d[8]; uint4 v[8];
        #pragma unroll
        for (int u = 0; u < 8; u++) n[u] = g_adj_e[j + u];
        #pragma unroll
        for (int u = 0; u < 8; u++) d[u] = g_dv[n[u]];
        #pragma unroll
        for (int u = 0; u < 8; u++)
            v[u] = *(const uint4*)&g_Zh[(size_t)n[u] * DIM + lane * 8];
        #pragma unroll
        for (int u = 0; u < 8; u++) acc8(a, v[u], d[u]);
    }
    for (; j < e; j++) {
        int n0 = g_adj_e[j];
        float d0 = g_dv[n0];
        uint4 v0 = *(const uint4*)&g_Zh[(size_t)n0 * DIM + lane * 8];
        acc8(a, v0, d0);
    }
    float de = g_de[w];
    __half2 o0 = __floats2half2_rn(a[0] * de, a[1] * de);
    __half2 o1 = __floats2half2_rn(a[2] * de, a[3] * de);
    __half2 o2 = __floats2half2_rn(a[4] * de, a[5] * de);
    __half2 o3 = __floats2half2_rn(a[6] * de, a[7] * de);
    uint4 st;
    st.x = *(uint32_t*)&o0; st.y = *(uint32_t*)&o1;
    st.z = *(uint32_t*)&o2; st.w = *(uint32_t*)&o3;
    *(uint4*)&g_S2h[(size_t)w * DIM + lane * 8] = st;
}

// ---------------- out[n] = d_v[n] * sum_{e of n} S2h[e]  (fp32 out) ----------
// pairwise fp16 pre-reduction halves conversion work; streaming stores.
__global__ void node_gather_kernel(float* __restrict__ out_g) {
    int w    = (blockIdx.x * blockDim.x + threadIdx.x) >> 5;
    int lane = threadIdx.x & 31;
    if (w >= N_NODES) return;
    int s = g_off_n[w], e = g_off_n[w + 1];
    float a[8] = {0.f, 0.f, 0.f, 0.f, 0.f, 0.f, 0.f, 0.f};
    int j = s;
    int lim8 = s + ((e - s) & ~7);
    for (; j < lim8; j += 8) {
        int ee[8]; uint4 v[8];
        #pragma unroll
        for (int u = 0; u < 8; u++) ee[u] = g_adj_n[j + u];
        #pragma unroll
        for (int u = 0; u < 8; u++)
            v[u] = *(const uint4*)&g_S2h[(size_t)ee[u] * DIM + lane * 8];
        accp(a, v[0], v[1]); accp(a, v[2], v[3]);
        accp(a, v[4], v[5]); accp(a, v[6], v[7]);
    }
    for (; j < e; j++) {
        int e0 = g_adj_n[j];
        uint4 v0 = *(const uint4*)&g_S2h[(size_t)e0 * DIM + lane * 8];
        acc8(a, v0, 1.0f);
    }
    float dv = g_dv[w];
    float4 o0, o1;
    o0.x = a[0] * dv; o0.y = a[1] * dv; o0.z = a[2] * dv; o0.w = a[3] * dv;
    o1.x = a[4] * dv; o1.y = a[5] * dv; o1.z = a[6] * dv; o1.w = a[7] * dv;
    float* dst = out_g + (size_t)w * DIM + lane * 8;
    __stcs((float4*)dst, o0);
    __stcs((float4*)(dst + 4), o1);
}

// ---------------- launch (3-way fork/join DAG) -------------------------------
extern "C" void kernel_launch(void* const* d_in, const int* in_sizes, int n_in,
                              void* d_out, int out_size) {
    const float* X  = (const float*)d_in[0];
    const void*  ni = d_in[1];
    const void*  ei = d_in[2];
    const float* W  = (const float*)d_in[3];
    const float* b  = (const float*)d_in[4];
    float* out = (float*)d_out;

    static cudaStream_t sB = nullptr, sC = nullptr;
    static cudaEvent_t evRoot = nullptr, evB = nullptr, evD = nullptr,
                       evCV = nullptr, evScan = nullptr, evC = nullptr;
    if (sB == nullptr) {
        cudaStreamCreateWithFlags(&sB, cudaStreamNonBlocking);
        cudaStreamCreateWithFlags(&sC, cudaStreamNonBlocking);
        cudaEventCreateWithFlags(&evRoot, cudaEventDisableTiming);
        cudaEventCreateWithFlags(&evB, cudaEventDisableTiming);
        cudaEventCreateWithFlags(&evD, cudaEventDisableTiming);
        cudaEventCreateWithFlags(&evCV, cudaEventDisableTiming);
        cudaEventCreateWithFlags(&evScan, cudaEventDisableTiming);
        cudaEventCreateWithFlags(&evC, cudaEventDisableTiming);
    }

    // fork: sB branches off the main (capture) stream at the root
    cudaEventRecord(evRoot, 0);
    cudaStreamWaitEvent(sB, evRoot, 0);

    // ---- chain B (sB): W transpose/round + tf32 GEMM ----
    convert_w_kernel<<<DIM, DIM, 0, sB>>>(W);
    dim3 ggrid(N_PAD / 128, DIM / 128);
    gemm_tf32_kernel<<<ggrid, 256, 0, sB>>>(X, b);
    cudaEventRecord(evB, sB);

    // ---- chain A (main): detect, then count_e || count_v(sC) ----
    detect_kernel<<<1, 32>>>(ni);
    cudaEventRecord(evD, 0);
    cudaStreamWaitEvent(sC, evD, 0);
    count_v_kernel<<<(NNZ + 255) / 256, 256, 0, sC>>>(ni);
    cudaEventRecord(evCV, sC);
    count_e_kernel<<<(NNZ + 255) / 256, 256>>>(ei);
    cudaStreamWaitEvent(0, evCV, 0);

    // scans (both v and e)
    scan_p1_kernel<<<dim3(CH_N, 2), 1024>>>();
    scan_p2_kernel<<<1, 128>>>();
    scan_p3_kernel<<<dim3(CH_N, 2), 1024>>>();
    cudaEventRecord(evScan, 0);

    // ---- chain C (sC): node-side fill + counter re-zero, overlapped ----
    cudaStreamWaitEvent(sC, evScan, 0);
    fill_n_kernel<<<(NNZ / 4 + 255) / 256, 256, 0, sC>>>(ni, ei);
    zero_kernel<<<(N_NODES + 255) / 256, 256, 0, sC>>>();
    cudaEventRecord(evC, sC);

    // ---- chain A continues: edge-side fill (atomic-free) ----
    fill_e_kernel<<<(NNZ / 4 + 255) / 256, 256>>>(ni, ei);

    // join GEMM, then edge gather
    cudaStreamWaitEvent(0, evB, 0);
    edge_gather_kernel<<<(N_EDGES * 32 + 255) / 256, 256>>>();

    // join chain C, then node gather
    cudaStreamWaitEvent(0, evC, 0);
    node_gather_kernel<<<(N_NODES * 32 + 255) / 256, 256>>>(out);
}

// round 15
// speedup vs baseline: 1.4815x; 1.4815x over previous
#include <cuda_runtime.h>
#include <cuda_bf16.h>
#include <cuda_fp16.h>
#include <cstdint>

#define N_NODES 50000
#define N_PAD   50048              // 391 * 128
#define N_EDGES 25000
#define NNZ     800000
#define DIM     256

#define CH_E ((N_EDGES + 1023) / 1024)   // 25
#define CH_N ((N_NODES + 1023) / 1024)   // 49

// ---------------- scratch ----------------------------------------------------
__device__ __align__(16) __half g_Zh [N_NODES * DIM];     // fp16(X@W + b)  25.6MB
__device__ __align__(16) __half g_S2h[N_EDGES * DIM];     // fp16 step2     12.8MB
__device__ __align__(16) float  g_Wt [DIM * DIM];         // tf32-rounded W^T [n][k]
__device__ int   g_deg_v[N_NODES];
__device__ int   g_deg_e[N_EDGES];
__device__ float g_dv[N_NODES];
__device__ float g_de[N_EDGES];
__device__ int   g_off_e[N_EDGES + 1];
__device__ int   g_off_n[N_NODES + 1];
__device__ int   g_rank_v[NNZ];           // rank of nnz i within its node segment
__device__ int   g_rank_e[NNZ];           // rank of nnz i within its edge segment
__device__ int   g_adj_e[NNZ];
__device__ int   g_adj_n[NNZ];
__device__ int   g_part_e[32];
__device__ int   g_part_n[64];
__device__ int   g_is64;

// ---------------- helpers ----------------------------------------------------
__device__ __forceinline__ int idx_at(const void* p, int i, int is64) {
    if (is64) return (int)(((const long long*)p)[i]);
    return ((const int*)p)[i];
}
__device__ __forceinline__ uint32_t f2tf32(float f) {
    uint32_t r;
    asm("cvt.rna.tf32.f32 %0, %1;" : "=r"(r) : "f"(f));
    return r;
}
__device__ __forceinline__ void mma_tf32(float* c, uint32_t a0, uint32_t a1,
                                         uint32_t a2, uint32_t a3,
                                         uint32_t b0, uint32_t b1) {
    asm volatile(
        "mma.sync.aligned.m16n8k8.row.col.f32.tf32.tf32.f32 "
        "{%0,%1,%2,%3}, {%4,%5,%6,%7}, {%8,%9}, {%0,%1,%2,%3};\n"
        : "+f"(c[0]), "+f"(c[1]), "+f"(c[2]), "+f"(c[3])
        : "r"(a0), "r"(a1), "r"(a2), "r"(a3), "r"(b0), "r"(b1));
}
// accumulate 8 fp16 lanes (one uint4) into float acc[8], scaled by s
__device__ __forceinline__ void acc8(float* a, uint4 v, float s) {
    __half2 h0 = *(__half2*)&v.x, h1 = *(__half2*)&v.y;
    __half2 h2 = *(__half2*)&v.z, h3 = *(__half2*)&v.w;
    float2 f0 = __half22float2(h0), f1 = __half22float2(h1);
    float2 f2 = __half22float2(h2), f3 = __half22float2(h3);
    a[0] = fmaf(f0.x, s, a[0]); a[1] = fmaf(f0.y, s, a[1]);
    a[2] = fmaf(f1.x, s, a[2]); a[3] = fmaf(f1.y, s, a[3]);
    a[4] = fmaf(f2.x, s, a[4]); a[5] = fmaf(f2.y, s, a[5]);
    a[6] = fmaf(f3.x, s, a[6]); a[7] = fmaf(f3.y, s, a[7]);
}

// ---------------- detect index dtype (32 threads, 64 qwords) -----------------
__global__ void detect_kernel(const void* node_idx) {
    const unsigned long long* q = (const unsigned long long*)node_idx;
    int t = threadIdx.x;
    int bad = ((q[t] >> 32) != 0ull) || ((q[t + 32] >> 32) != 0ull);
    bad = __any_sync(0xffffffffu, bad);
    if (t == 0) g_is64 = bad ? 0 : 1;
}

// ---------------- zero degree counters (off critical path) -------------------
__global__ void zero_kernel() {
    int i = blockIdx.x * blockDim.x + threadIdx.x;
    if (i < N_NODES) g_deg_v[i] = 0;
    if (i < N_EDGES) g_deg_e[i] = 0;
}

// ---------------- degree histogram + per-nnz rank capture (1 nnz/thread) -----
__global__ void count_kernel(const void* ni, const void* ei) {
    int i = blockIdx.x * blockDim.x + threadIdx.x;
    if (i >= NNZ) return;
    int is64 = g_is64;
    int n = idx_at(ni, i, is64);
    int e = idx_at(ei, i, is64);
    g_rank_v[i] = atomicAdd(&g_deg_v[n], 1);
    g_rank_e[i] = atomicAdd(&g_deg_e[e], 1);
}

// ---------------- convert W -> transposed tf32-rounded fp32 ------------------
__global__ void convert_w_kernel(const float* __restrict__ W) {
    int n = blockIdx.x;
    int k = threadIdx.x;
    float w = W[(size_t)k * DIM + n];
    g_Wt[n * DIM + k] = __uint_as_float(f2tf32(w));
}

// ---------------- GEMM (single-pass tf32 tensor cores, A-reg prefetch) -------
// Zh = fp16(X @ W + b).  128x128 tile, K-chunks of 32, 8 warps (2m x 4n).
#define SAF 36
__global__ __launch_bounds__(256, 2)
void gemm_tf32_kernel(const float* __restrict__ X,
                      const float* __restrict__ bias) {
    __shared__ __align__(16) float As[128][SAF];
    __shared__ __align__(16) float Bs[128][SAF];

    int t    = threadIdx.x;
    int warp = t >> 5, lane = t & 31;
    int wm = warp >> 2, wn = warp & 3;
    int g  = lane >> 2, q = lane & 3;
    int m0 = blockIdx.x * 128;
    int n0 = blockIdx.y * 128;

    float acc[4][4][4];
    #pragma unroll
    for (int i = 0; i < 4; i++)
        #pragma unroll
        for (int j = 0; j < 4; j++)
            #pragma unroll
            for (int r = 0; r < 4; r++) acc[i][j][r] = 0.0f;

    int lrow = t >> 1;        // 0..127
    int lseg = t & 1;         // 16-float segment
    int gr = m0 + lrow;

    // prefetch A chunk 0 into registers
    float vf[16];
    {
        if (gr < N_NODES) {
            const float4* src = (const float4*)&X[(size_t)gr * DIM + 0 + lseg * 16];
            float4 f0 = src[0], f1 = src[1], f2 = src[2], f3 = src[3];
            vf[0]=f0.x; vf[1]=f0.y; vf[2]=f0.z; vf[3]=f0.w;
            vf[4]=f1.x; vf[5]=f1.y; vf[6]=f1.z; vf[7]=f1.w;
            vf[8]=f2.x; vf[9]=f2.y; vf[10]=f2.z; vf[11]=f2.w;
            vf[12]=f3.x; vf[13]=f3.y; vf[14]=f3.z; vf[15]=f3.w;
        } else {
            #pragma unroll
            for (int k = 0; k < 16; k++) vf[k] = 0.0f;
        }
    }

    for (int k0 = 0; k0 < DIM; k0 += 32) {
        // A: tf32-round prefetched regs -> smem
        {
            uint32_t tv[16];
            #pragma unroll
            for (int k = 0; k < 16; k++) tv[k] = f2tf32(vf[k]);
            #pragma unroll
            for (int p = 0; p < 4; p++)
                *(uint4*)&As[lrow][lseg * 16 + p * 4] = ((uint4*)tv)[p];
        }
        // B: copy from L2-resident pre-rounded g_Wt
        {
            const float4* src = (const float4*)&g_Wt[(n0 + lrow) * DIM + k0 + lseg * 16];
            #pragma unroll
            for (int p = 0; p < 4; p++)
                *(float4*)&Bs[lrow][lseg * 16 + p * 4] = src[p];
        }
        __syncthreads();

        // prefetch NEXT A chunk while MMAs run on this one
        if (k0 + 32 < DIM) {
            if (gr < N_NODES) {
                const float4* src = (const float4*)&X[(size_t)gr * DIM + k0 + 32 + lseg * 16];
                float4 f0 = src[0], f1 = src[1], f2 = src[2], f3 = src[3];
                vf[0]=f0.x; vf[1]=f0.y; vf[2]=f0.z; vf[3]=f0.w;
                vf[4]=f1.x; vf[5]=f1.y; vf[6]=f1.z; vf[7]=f1.w;
                vf[8]=f2.x; vf[9]=f2.y; vf[10]=f2.z; vf[11]=f2.w;
                vf[12]=f3.x; vf[13]=f3.y; vf[14]=f3.z; vf[15]=f3.w;
            }
        }

        #pragma unroll
        for (int ksub = 0; ksub < 32; ksub += 8) {
            uint32_t b0[4], b1[4];
            #pragma unroll
            for (int j = 0; j < 4; j++) {
                int nr = wn * 32 + j * 8 + g;
                b0[j] = *(const uint32_t*)&Bs[nr][ksub + q];
                b1[j] = *(const uint32_t*)&Bs[nr][ksub + q + 4];
            }
            #pragma unroll
            for (int i = 0; i < 4; i++) {
                int mr = wm * 64 + i * 16;
                uint32_t a0 = *(const uint32_t*)&As[mr + g][ksub + q];
                uint32_t a1 = *(const uint32_t*)&As[mr + 8 + g][ksub + q];
                uint32_t a2 = *(const uint32_t*)&As[mr + g][ksub + q + 4];
                uint32_t a3 = *(const uint32_t*)&As[mr + 8 + g][ksub + q + 4];
                #pragma unroll
                for (int j = 0; j < 4; j++)
                    mma_tf32(acc[i][j], a0, a1, a2, a3, b0[j], b1[j]);
            }
        }
        __syncthreads();
    }

    // epilogue: + bias, store fp16 Zh
    #pragma unroll
    for (int j = 0; j < 4; j++) {
        int cb = n0 + wn * 32 + j * 8 + q * 2;
        float2 bb = *(const float2*)&bias[cb];
        #pragma unroll
        for (int i = 0; i < 4; i++) {
            int r = m0 + wm * 64 + i * 16 + g;
            if (r < N_NODES) {
                __half2 o = __floats2half2_rn(acc[i][j][0] + bb.x, acc[i][j][1] + bb.y);
                *(__half2*)&g_Zh[(size_t)r * DIM + cb] = o;
            }
            if (r + 8 < N_NODES) {
                __half2 o = __floats2half2_rn(acc[i][j][2] + bb.x, acc[i][j][3] + bb.y);
                *(__half2*)&g_Zh[(size_t)(r + 8) * DIM + cb] = o;
            }
        }
    }
}

// ---------------- scan phase 1 -----------------------------------------------
__global__ void scan_p1_kernel() {
    int which = blockIdx.y;
    int n          = which ? N_NODES : N_EDGES;
    const int* deg = which ? g_deg_v : g_deg_e;
    int*  off      = which ? g_off_n : g_off_e;
    float* dinv    = which ? g_dv    : g_de;
    int*  part     = which ? g_part_n : g_part_e;

    int base = blockIdx.x * 1024;
    if (base >= n) return;
    int tid = threadIdx.x;
    int i = base + tid;
    int v = (i < n) ? deg[i] : 0;

    int x = v;
    int lane = tid & 31, warp = tid >> 5;
    #pragma unroll
    for (int s = 1; s < 32; s <<= 1) {
        int t = __shfl_up_sync(0xffffffffu, x, s);
        if (lane >= s) x += t;
    }
    __shared__ int wsum[32];
    if (lane == 31) wsum[warp] = x;
    __syncthreads();
    if (warp == 0) {
        int y = wsum[lane];
        #pragma unroll
        for (int s = 1; s < 32; s <<= 1) {
            int t = __shfl_up_sync(0xffffffffu, y, s);
            if (lane >= s) y += t;
        }
        wsum[lane] = y;
    }
    __syncthreads();
    int incl = x + (warp ? wsum[warp - 1] : 0);
    if (i < n) {
        off[i] = incl - v;
        dinv[i] = (v > 0) ? (which ? rsqrtf((float)v) : 1.0f / (float)v) : 0.0f;
    }
    if (tid == 1023) part[blockIdx.x] = incl;
}

// ---------------- scan phase 2 -----------------------------------------------
__global__ void scan_p2_kernel() {
    __shared__ int pe[32], pn[64];
    int t = threadIdx.x;
    if (t < 32) pe[t] = (t < CH_E) ? g_part_e[t] : 0;
    if (t < 64) pn[t] = (t < CH_N) ? g_part_n[t] : 0;
    __syncthreads();
    #pragma unroll
    for (int s = 1; s < 64; s <<= 1) {
        int ve = (t < 32 && t >= s) ? pe[t - s] : 0;
        int vn = (t < 64 && t >= s) ? pn[t - s] : 0;
        __syncthreads();
        if (t < 32) pe[t] += ve;
        if (t < 64) pn[t] += vn;
        __syncthreads();
    }
    if (t < 32) g_part_e[t] = t ? pe[t - 1] : 0;
    if (t < 64) g_part_n[t] = t ? pn[t - 1] : 0;
    if (t == 0) { g_off_e[N_EDGES] = NNZ; g_off_n[N_NODES] = NNZ; }
}

// ---------------- scan phase 3 -----------------------------------------------
__global__ void scan_p3_kernel() {
    int which = blockIdx.y;
    int n    = which ? N_NODES : N_EDGES;
    int* off = which ? g_off_n : g_off_e;
    int i = blockIdx.x * 1024 + threadIdx.x;
    if (i < n) off[i] += (which ? g_part_n : g_part_e)[blockIdx.x];
}

// ---------------- CSR fill, edge side (atomic-free via ranks) ----------------
__global__ void fill_e_kernel(const void* ni, const void* ei) {
    int base = (blockIdx.x * blockDim.x + threadIdx.x) * 4;
    if (base >= NNZ) return;
    int is64 = g_is64;
    int n[4], e[4], r[4];
    #pragma unroll
    for (int u = 0; u < 4; u++) n[u] = idx_at(ni, base + u, is64);
    #pragma unroll
    for (int u = 0; u < 4; u++) e[u] = idx_at(ei, base + u, is64);
    #pragma unroll
    for (int u = 0; u < 4; u++) r[u] = g_rank_e[base + u];
    #pragma unroll
    for (int u = 0; u < 4; u++)
        g_adj_e[g_off_e[e[u]] + r[u]] = n[u];
}

// ---------------- CSR fill, node side (atomic-free via ranks) ----------------
__global__ void fill_n_kernel(const void* ni, const void* ei) {
    int base = (blockIdx.x * blockDim.x + threadIdx.x) * 4;
    if (base >= NNZ) return;
    int is64 = g_is64;
    int n[4], e[4], r[4];
    #pragma unroll
    for (int u = 0; u < 4; u++) n[u] = idx_at(ni, base + u, is64);
    #pragma unroll
    for (int u = 0; u < 4; u++) e[u] = idx_at(ei, base + u, is64);
    #pragma unroll
    for (int u = 0; u < 4; u++) r[u] = g_rank_v[base + u];
    #pragma unroll
    for (int u = 0; u < 4; u++)
        g_adj_n[g_off_n[n[u]] + r[u]] = e[u];
}

// ---------------- S2h[e] = fp16( d_e * sum_{n in e} d_v[n] * Zh[n] ) ---------
__global__ void edge_gather_kernel() {
    int w    = (blockIdx.x * blockDim.x + threadIdx.x) >> 5;
    int lane = threadIdx.x & 31;
    if (w >= N_EDGES) return;
    int s = g_off_e[w], e = g_off_e[w + 1];
    float a[8] = {0.f, 0.f, 0.f, 0.f, 0.f, 0.f, 0.f, 0.f};
    int j = s;
    int lim8 = s + ((e - s) & ~7);
    for (; j < lim8; j += 8) {
        int   n[8]; float d[8]; uint4 v[8];
        #pragma unroll
        for (int u = 0; u < 8; u++) n[u] = g_adj_e[j + u];
        #pragma unroll
        for (int u = 0; u < 8; u++) d[u] = g_dv[n[u]];
        #pragma unroll
        for (int u = 0; u < 8; u++)
            v[u] = *(const uint4*)&g_Zh[(size_t)n[u] * DIM + lane * 8];
        #pragma unroll
        for (int u = 0; u < 8; u++) acc8(a, v[u], d[u]);
    }
    for (; j < e; j++) {
        int n0 = g_adj_e[j];
        float d0 = g_dv[n0];
        uint4 v0 = *(const uint4*)&g_Zh[(size_t)n0 * DIM + lane * 8];
        acc8(a, v0, d0);
    }
    float de = g_de[w];
    __half2 o0 = __floats2half2_rn(a[0] * de, a[1] * de);
    __half2 o1 = __floats2half2_rn(a[2] * de, a[3] * de);
    __half2 o2 = __floats2half2_rn(a[4] * de, a[5] * de);
    __half2 o3 = __floats2half2_rn(a[6] * de, a[7] * de);
    uint4 st;
    st.x = *(uint32_t*)&o0; st.y = *(uint32_t*)&o1;
    st.z = *(uint32_t*)&o2; st.w = *(uint32_t*)&o3;
    *(uint4*)&g_S2h[(size_t)w * DIM + lane * 8] = st;
}

// ---------------- out[n] = d_v[n] * sum_{e of n} S2h[e]  (fp32 out) ----------
__global__ void node_gather_kernel(float* __restrict__ out_g) {
    int w    = (blockIdx.x * blockDim.x + threadIdx.x) >> 5;
    int lane = threadIdx.x & 31;
    if (w >= N_NODES) return;
    int s = g_off_n[w], e = g_off_n[w + 1];
    float a[8] = {0.f, 0.f, 0.f, 0.f, 0.f, 0.f, 0.f, 0.f};
    int j = s;
    int lim8 = s + ((e - s) & ~7);
    for (; j < lim8; j += 8) {
        int ee[8]; uint4 v[8];
        #pragma unroll
        for (int u = 0; u < 8; u++) ee[u] = g_adj_n[j + u];
        #pragma unroll
        for (int u = 0; u < 8; u++)
            v[u] = *(const uint4*)&g_S2h[(size_t)ee[u] * DIM + lane * 8];
        #pragma unroll
        for (int u = 0; u < 8; u++) acc8(a, v[u], 1.0f);
    }
    for (; j < e; j++) {
        int e0 = g_adj_n[j];
        uint4 v0 = *(const uint4*)&g_S2h[(size_t)e0 * DIM + lane * 8];
        acc8(a, v0, 1.0f);
    }
    float dv = g_dv[w];
    float4 o0, o1;
    o0.x = a[0] * dv; o0.y = a[1] * dv; o0.z = a[2] * dv; o0.w = a[3] * dv;
    o1.x = a[4] * dv; o1.y = a[5] * dv; o1.z = a[6] * dv; o1.w = a[7] * dv;
    float* dst = out_g + (size_t)w * DIM + lane * 8;
    *(float4*)dst = o0;
    *(float4*)(dst + 4) = o1;
}

// ---------------- launch (3-way fork/join DAG, R12 structure) ----------------
extern "C" void kernel_launch(void* const* d_in, const int* in_sizes, int n_in,
                              void* d_out, int out_size) {
    const float* X  = (const float*)d_in[0];
    const void*  ni = d_in[1];
    const void*  ei = d_in[2];
    const float* W  = (const float*)d_in[3];
    const float* b  = (const float*)d_in[4];
    float* out = (float*)d_out;

    static cudaStream_t sB = nullptr, sC = nullptr;
    static cudaEvent_t evRoot = nullptr, evB = nullptr, evScan = nullptr, evC = nullptr;
    if (sB == nullptr) {
        cudaStreamCreateWithFlags(&sB, cudaStreamNonBlocking);
        cudaStreamCreateWithFlags(&sC, cudaStreamNonBlocking);
        cudaEventCreateWithFlags(&evRoot, cudaEventDisableTiming);
        cudaEventCreateWithFlags(&evB, cudaEventDisableTiming);
        cudaEventCreateWithFlags(&evScan, cudaEventDisableTiming);
        cudaEventCreateWithFlags(&evC, cudaEventDisableTiming);
    }

    // fork: sB branches off the main (capture) stream at the root
    cudaEventRecord(evRoot, 0);
    cudaStreamWaitEvent(sB, evRoot, 0);

    // ---- chain B (sB): W transpose/round + tf32 GEMM ----
    convert_w_kernel<<<DIM, DIM, 0, sB>>>(W);
    dim3 ggrid(N_PAD / 128, DIM / 128);
    gemm_tf32_kernel<<<ggrid, 256, 0, sB>>>(X, b);
    cudaEventRecord(evB, sB);

    // ---- chain A (main): detect -> count(+ranks, 1 nnz/thread) -> scans ----
    detect_kernel<<<1, 32>>>(ni);
    count_kernel<<<(NNZ + 255) / 256, 256>>>(ni, ei);
    scan_p1_kernel<<<dim3(CH_N, 2), 1024>>>();
    scan_p2_kernel<<<1, 128>>>();
    scan_p3_kernel<<<dim3(CH_N, 2), 1024>>>();
    cudaEventRecord(evScan, 0);

    // ---- chain C (sC): node-side fill + counter re-zero, overlapped ----
    cudaStreamWaitEvent(sC, evScan, 0);
    fill_n_kernel<<<(NNZ / 4 + 255) / 256, 256, 0, sC>>>(ni, ei);
    zero_kernel<<<(N_NODES + 255) / 256, 256, 0, sC>>>();
    cudaEventRecord(evC, sC);

    // ---- chain A continues: edge-side fill (atomic-free) ----
    fill_e_kernel<<<(NNZ / 4 + 255) / 256, 256>>>(ni, ei);

    // join GEMM, then edge gather
    cudaStreamWaitEvent(0, evB, 0);
    edge_gather_kernel<<<(N_EDGES * 32 + 255) / 256, 256>>>();

    // join chain C, then node gather
    cudaStreamWaitEvent(0, evC, 0);
    node_gather_kernel<<<(N_NODES * 32 + 255) / 256, 256>>>(out);
}

// round 16
// speedup vs baseline: 1.5187x; 1.0251x over previous
#include <cuda_runtime.h>
#include <cuda_bf16.h>
#include <cuda_fp16.h>
#include <cstdint>

#define N_NODES 50000
#define N_PAD   50048              // 391 * 128
#define N_EDGES 25000
#define NNZ     800000
#define DIM     256

#define CH_E ((N_EDGES + 1023) / 1024)   // 25
#define CH_N ((N_NODES + 1023) / 1024)   // 49

// ---------------- scratch ----------------------------------------------------
__device__ __align__(16) __half g_Zh [N_NODES * DIM];     // fp16(X@W + b)  25.6MB
__device__ __align__(16) __half g_S2h[N_EDGES * DIM];     // fp16 step2     12.8MB
__device__ __align__(16) float  g_Wt [DIM * DIM];         // tf32-rounded W^T [n][k]
__device__ int   g_deg_v[N_NODES];
__device__ int   g_deg_e[N_EDGES];
__device__ float g_dv[N_NODES];
__device__ float g_de[N_EDGES];
__device__ int   g_off_e[N_EDGES + 1];
__device__ int   g_off_n[N_NODES + 1];
__device__ int   g_rank_v[NNZ];
__device__ int   g_rank_e[NNZ];
__device__ int   g_adj_e[NNZ];
__device__ int   g_adj_n[NNZ];
__device__ int   g_part_e[32];
__device__ int   g_part_n[64];
__device__ int   g_is64;

// ---------------- helpers ----------------------------------------------------
__device__ __forceinline__ int idx_at(const void* p, int i, int is64) {
    if (is64) return (int)(((const long long*)p)[i]);
    return ((const int*)p)[i];
}
__device__ __forceinline__ uint32_t f2tf32(float f) {
    uint32_t r;
    asm("cvt.rna.tf32.f32 %0, %1;" : "=r"(r) : "f"(f));
    return r;
}
__device__ __forceinline__ void mma_tf32(float* c, uint32_t a0, uint32_t a1,
                                         uint32_t a2, uint32_t a3,
                                         uint32_t b0, uint32_t b1) {
    asm volatile(
        "mma.sync.aligned.m16n8k8.row.col.f32.tf32.tf32.f32 "
        "{%0,%1,%2,%3}, {%4,%5,%6,%7}, {%8,%9}, {%0,%1,%2,%3};\n"
        : "+f"(c[0]), "+f"(c[1]), "+f"(c[2]), "+f"(c[3])
        : "r"(a0), "r"(a1), "r"(a2), "r"(a3), "r"(b0), "r"(b1));
}
__device__ __forceinline__ void cp_async16(void* smem_dst, const void* gsrc) {
    uint32_t s;
    asm("{ .reg .u64 t; cvta.to.shared.u64 t, %1; cvt.u32.u64 %0, t; }"
        : "=r"(s) : "l"(smem_dst));
    asm volatile("cp.async.cg.shared.global [%0], [%1], 16;" :: "r"(s), "l"(gsrc));
}
// accumulate 8 fp16 lanes (one uint4) into float acc[8], scaled by s
__device__ __forceinline__ void acc8(float* a, uint4 v, float s) {
    __half2 h0 = *(__half2*)&v.x, h1 = *(__half2*)&v.y;
    __half2 h2 = *(__half2*)&v.z, h3 = *(__half2*)&v.w;
    float2 f0 = __half22float2(h0), f1 = __half22float2(h1);
    float2 f2 = __half22float2(h2), f3 = __half22float2(h3);
    a[0] = fmaf(f0.x, s, a[0]); a[1] = fmaf(f0.y, s, a[1]);
    a[2] = fmaf(f1.x, s, a[2]); a[3] = fmaf(f1.y, s, a[3]);
    a[4] = fmaf(f2.x, s, a[4]); a[5] = fmaf(f2.y, s, a[5]);
    a[6] = fmaf(f3.x, s, a[6]); a[7] = fmaf(f3.y, s, a[7]);
}

// ---------------- detect index dtype (32 threads, 64 qwords) -----------------
__global__ void detect_kernel(const void* node_idx) {
    const unsigned long long* q = (const unsigned long long*)node_idx;
    int t = threadIdx.x;
    int bad = ((q[t] >> 32) != 0ull) || ((q[t + 32] >> 32) != 0ull);
    bad = __any_sync(0xffffffffu, bad);
    if (t == 0) g_is64 = bad ? 0 : 1;
}

// ---------------- zero degree counters (off critical path, side stream) ------
__global__ void zero_kernel() {
    int i = blockIdx.x * blockDim.x + threadIdx.x;
    if (i < N_NODES) g_deg_v[i] = 0;
    if (i < N_EDGES) g_deg_e[i] = 0;
}

// ---------------- degree histogram + rank capture, split per side ------------
__global__ void count_e_kernel(const void* ei) {
    int i = blockIdx.x * blockDim.x + threadIdx.x;
    if (i >= NNZ) return;
    int e = idx_at(ei, i, g_is64);
    g_rank_e[i] = atomicAdd(&g_deg_e[e], 1);
}
__global__ void count_v_kernel(const void* ni) {
    int i = blockIdx.x * blockDim.x + threadIdx.x;
    if (i >= NNZ) return;
    int n = idx_at(ni, i, g_is64);
    g_rank_v[i] = atomicAdd(&g_deg_v[n], 1);
}

// ---------------- convert W -> transposed tf32-rounded fp32 ------------------
__global__ void convert_w_kernel(const float* __restrict__ W) {
    int n = blockIdx.x;
    int k = threadIdx.x;
    float w = W[(size_t)k * DIM + n];
    g_Wt[n * DIM + k] = __uint_as_float(f2tf32(w));
}

// ---------------- GEMM: tf32 tensor cores, A reg-prefetch, B cp.async db -----
// Zh = fp16(X @ W + b).  128x128 tile, K-chunks of 32, 8 warps (2m x 4n).
#define SAF 36
__global__ __launch_bounds__(256, 2)
void gemm_tf32_kernel(const float* __restrict__ X,
                      const float* __restrict__ bias) {
    __shared__ __align__(16) float As[128][SAF];
    __shared__ __align__(16) float Bs[2][128][SAF];

    int t    = threadIdx.x;
    int warp = t >> 5, lane = t & 31;
    int wm = warp >> 2, wn = warp & 3;
    int g  = lane >> 2, q = lane & 3;
    int m0 = blockIdx.x * 128;
    int n0 = blockIdx.y * 128;

    float acc[4][4][4];
    #pragma unroll
    for (int i = 0; i < 4; i++)
        #pragma unroll
        for (int j = 0; j < 4; j++)
            #pragma unroll
            for (int r = 0; r < 4; r++) acc[i][j][r] = 0.0f;

    int lrow = t >> 1;        // 0..127
    int lseg = t & 1;         // 16-float segment
    int gr = m0 + lrow;

    // issue cp.async for B chunk 0 into Bs[0]
    {
        const float* bsrc = &g_Wt[(n0 + lrow) * DIM + 0 + lseg * 16];
        #pragma unroll
        for (int p = 0; p < 4; p++)
            cp_async16(&Bs[0][lrow][lseg * 16 + p * 4], bsrc + p * 4);
        asm volatile("cp.async.commit_group;" ::: "memory");
    }

    // prefetch A chunk 0 into registers
    float vf[16];
    {
        if (gr < N_NODES) {
            const float4* src = (const float4*)&X[(size_t)gr * DIM + 0 + lseg * 16];
            float4 f0 = src[0], f1 = src[1], f2 = src[2], f3 = src[3];
            vf[0]=f0.x; vf[1]=f0.y; vf[2]=f0.z; vf[3]=f0.w;
            vf[4]=f1.x; vf[5]=f1.y; vf[6]=f1.z; vf[7]=f1.w;
            vf[8]=f2.x; vf[9]=f2.y; vf[10]=f2.z; vf[11]=f2.w;
            vf[12]=f3.x; vf[13]=f3.y; vf[14]=f3.z; vf[15]=f3.w;
        } else {
            #pragma unroll
            for (int k = 0; k < 16; k++) vf[k] = 0.0f;
        }
    }

    #pragma unroll
    for (int kc = 0; kc < 8; kc++) {
        int k0 = kc * 32;
        int buf = kc & 1;
        // A: tf32-round prefetched regs -> smem
        {
            uint32_t tv[16];
            #pragma unroll
            for (int k = 0; k < 16; k++) tv[k] = f2tf32(vf[k]);
            #pragma unroll
            for (int p = 0; p < 4; p++)
                *(uint4*)&As[lrow][lseg * 16 + p * 4] = ((uint4*)tv)[p];
        }
        // issue cp.async for NEXT B chunk into the other buffer
        if (kc < 7) {
            const float* bsrc = &g_Wt[(n0 + lrow) * DIM + k0 + 32 + lseg * 16];
            #pragma unroll
            for (int p = 0; p < 4; p++)
                cp_async16(&Bs[buf ^ 1][lrow][lseg * 16 + p * 4], bsrc + p * 4);
            asm volatile("cp.async.commit_group;" ::: "memory");
            asm volatile("cp.async.wait_group 1;" ::: "memory");
        } else {
            asm volatile("cp.async.wait_group 0;" ::: "memory");
        }
        __syncthreads();

        // prefetch NEXT A chunk while MMAs run on this one
        if (kc < 7) {
            if (gr < N_NODES) {
                const float4* src = (const float4*)&X[(size_t)gr * DIM + k0 + 32 + lseg * 16];
                float4 f0 = src[0], f1 = src[1], f2 = src[2], f3 = src[3];
                vf[0]=f0.x; vf[1]=f0.y; vf[2]=f0.z; vf[3]=f0.w;
                vf[4]=f1.x; vf[5]=f1.y; vf[6]=f1.z; vf[7]=f1.w;
                vf[8]=f2.x; vf[9]=f2.y; vf[10]=f2.z; vf[11]=f2.w;
                vf[12]=f3.x; vf[13]=f3.y; vf[14]=f3.z; vf[15]=f3.w;
            }
        }

        #pragma unroll
        for (int ksub = 0; ksub < 32; ksub += 8) {
            uint32_t b0[4], b1[4];
            #pragma unroll
            for (int j = 0; j < 4; j++) {
                int nr = wn * 32 + j * 8 + g;
                b0[j] = *(const uint32_t*)&Bs[buf][nr][ksub + q];
                b1[j] = *(const uint32_t*)&Bs[buf][nr][ksub + q + 4];
            }
            #pragma unroll
            for (int i = 0; i < 4; i++) {
                int mr = wm * 64 + i * 16;
                uint32_t a0 = *(const uint32_t*)&As[mr + g][ksub + q];
                uint32_t a1 = *(const uint32_t*)&As[mr + 8 + g][ksub + q];
                uint32_t a2 = *(const uint32_t*)&As[mr + g][ksub + q + 4];
                uint32_t a3 = *(const uint32_t*)&As[mr + 8 + g][ksub + q + 4];
                #pragma unroll
                for (int j = 0; j < 4; j++)
                    mma_tf32(acc[i][j], a0, a1, a2, a3, b0[j], b1[j]);
            }
        }
        __syncthreads();
    }

    // epilogue: + bias, store fp16 Zh
    #pragma unroll
    for (int j = 0; j < 4; j++) {
        int cb = n0 + wn * 32 + j * 8 + q * 2;
        float2 bb = *(const float2*)&bias[cb];
        #pragma unroll
        for (int i = 0; i < 4; i++) {
            int r = m0 + wm * 64 + i * 16 + g;
            if (r < N_NODES) {
                __half2 o = __floats2half2_rn(acc[i][j][0] + bb.x, acc[i][j][1] + bb.y);
                *(__half2*)&g_Zh[(size_t)r * DIM + cb] = o;
            }
            if (r + 8 < N_NODES) {
                __half2 o = __floats2half2_rn(acc[i][j][2] + bb.x, acc[i][j][3] + bb.y);
                *(__half2*)&g_Zh[(size_t)(r + 8) * DIM + cb] = o;
            }
        }
    }
}

// ---------------- scan phase 1 (parametrized side) ---------------------------
__global__ void scan_p1_kernel(int which) {
    int n          = which ? N_NODES : N_EDGES;
    const int* deg = which ? g_deg_v : g_deg_e;
    int*  off      = which ? g_off_n : g_off_e;
    float* dinv    = which ? g_dv    : g_de;
    int*  part     = which ? g_part_n : g_part_e;

    int base = blockIdx.x * 1024;
    if (base >= n) return;
    int tid = threadIdx.x;
    int i = base + tid;
    int v = (i < n) ? deg[i] : 0;

    int x = v;
    int lane = tid & 31, warp = tid >> 5;
    #pragma unroll
    for (int s = 1; s < 32; s <<= 1) {
        int t = __shfl_up_sync(0xffffffffu, x, s);
        if (lane >= s) x += t;
    }
    __shared__ int wsum[32];
    if (lane == 31) wsum[warp] = x;
    __syncthreads();
    if (warp == 0) {
        int y = wsum[lane];
        #pragma unroll
        for (int s = 1; s < 32; s <<= 1) {
            int t = __shfl_up_sync(0xffffffffu, y, s);
            if (lane >= s) y += t;
        }
        wsum[lane] = y;
    }
    __syncthreads();
    int incl = x + (warp ? wsum[warp - 1] : 0);
    if (i < n) {
        off[i] = incl - v;
        dinv[i] = (v > 0) ? (which ? rsqrtf((float)v) : 1.0f / (float)v) : 0.0f;
    }
    if (tid == 1023) part[blockIdx.x] = incl;
}

// ---------------- scan phase 2 (parametrized side) ---------------------------
__global__ void scan_p2_kernel(int which) {
    __shared__ int p[64];
    int t = threadIdx.x;
    int nch = which ? CH_N : CH_E;
    int* part = which ? g_part_n : g_part_e;
    p[t] = (t < nch) ? part[t] : 0;
    __syncthreads();
    #pragma unroll
    for (int s = 1; s < 64; s <<= 1) {
        int v = (t >= s) ? p[t - s] : 0;
        __syncthreads();
        p[t] += v;
        __syncthreads();
    }
    part[t] = t ? p[t - 1] : 0;     // exclusive
    if (t == 0) {
        if (which) g_off_n[N_NODES] = NNZ;
        else       g_off_e[N_EDGES] = NNZ;
    }
}

// ---------------- scan phase 3 (parametrized side) ---------------------------
__global__ void scan_p3_kernel(int which) {
    int n    = which ? N_NODES : N_EDGES;
    int* off = which ? g_off_n : g_off_e;
    int i = blockIdx.x * 1024 + threadIdx.x;
    if (i < n) off[i] += (which ? g_part_n : g_part_e)[blockIdx.x];
}

// ---------------- CSR fill, edge side (atomic-free via ranks) ----------------
__global__ void fill_e_kernel(const void* ni, const void* ei) {
    int base = (blockIdx.x * blockDim.x + threadIdx.x) * 4;
    if (base >= NNZ) return;
    int is64 = g_is64;
    int n[4], e[4], r[4];
    #pragma unroll
    for (int u = 0; u < 4; u++) n[u] = idx_at(ni, base + u, is64);
    #pragma unroll
    for (int u = 0; u < 4; u++) e[u] = idx_at(ei, base + u, is64);
    #pragma unroll
    for (int u = 0; u < 4; u++) r[u] = g_rank_e[base + u];
    #pragma unroll
    for (int u = 0; u < 4; u++)
        g_adj_e[g_off_e[e[u]] + r[u]] = n[u];
}

// ---------------- CSR fill, node side (atomic-free via ranks) ----------------
__global__ void fill_n_kernel(const void* ni, const void* ei) {
    int base = (blockIdx.x * blockDim.x + threadIdx.x) * 4;
    if (base >= NNZ) return;
    int is64 = g_is64;
    int n[4], e[4], r[4];
    #pragma unroll
    for (int u = 0; u < 4; u++) n[u] = idx_at(ni, base + u, is64);
    #pragma unroll
    for (int u = 0; u < 4; u++) e[u] = idx_at(ei, base + u, is64);
    #pragma unroll
    for (int u = 0; u < 4; u++) r[u] = g_rank_v[base + u];
    #pragma unroll
    for (int u = 0; u < 4; u++)
        g_adj_n[g_off_n[n[u]] + r[u]] = e[u];
}

// ---------------- S2h[e] = fp16( d_e * sum_{n in e} d_v[n] * Zh[n] ) ---------
__global__ void edge_gather_kernel() {
    int w    = (blockIdx.x * blockDim.x + threadIdx.x) >> 5;
    int lane = threadIdx.x & 31;
    if (w >= N_EDGES) return;
    int s = g_off_e[w], e = g_off_e[w + 1];
    float a[8] = {0.f, 0.f, 0.f, 0.f, 0.f, 0.f, 0.f, 0.f};
    int j = s;
    int lim8 = s + ((e - s) & ~7);
    for (; j < lim8; j += 8) {
        int   n[8]; float d[8]; uint4 v[8];
        #pragma unroll
        for (int u = 0; u < 8; u++) n[u] = g_adj_e[j + u];
        #pragma unroll
        for (int u = 0; u < 8; u++) d[u] = g_dv[n[u]];
        #pragma unroll
        for (int u = 0; u < 8; u++)
            v[u] = *(const uint4*)&g_Zh[(size_t)n[u] * DIM + lane * 8];
        #pragma unroll
        for (int u = 0; u < 8; u++) acc8(a, v[u], d[u]);
    }
    for (; j < e; j++) {
        int n0 = g_adj_e[j];
        float d0 = g_dv[n0];
        uint4 v0 = *(const uint4*)&g_Zh[(size_t)n0 * DIM + lane * 8];
        acc8(a, v0, d0);
    }
    float de = g_de[w];
    __half2 o0 = __floats2half2_rn(a[0] * de, a[1] * de);
    __half2 o1 = __floats2half2_rn(a[2] * de, a[3] * de);
    __half2 o2 = __floats2half2_rn(a[4] * de, a[5] * de);
    __half2 o3 = __floats2half2_rn(a[6] * de, a[7] * de);
    uint4 st;
    st.x = *(uint32_t*)&o0; st.y = *(uint32_t*)&o1;
    st.z = *(uint32_t*)&o2; st.w = *(uint32_t*)&o3;
    *(uint4*)&g_S2h[(size_t)w * DIM + lane * 8] = st;
}

// ---------------- out[n] = d_v[n] * sum_{e of n} S2h[e]  (fp32 out) ----------
__global__ void node_gather_kernel(float* __restrict__ out_g) {
    int w    = (blockIdx.x * blockDim.x + threadIdx.x) >> 5;
    int lane = threadIdx.x & 31;
    if (w >= N_NODES) return;
    int s = g_off_n[w], e = g_off_n[w + 1];
    float a[8] = {0.f, 0.f, 0.f, 0.f, 0.f, 0.f, 0.f, 0.f};
    int j = s;
    int lim8 = s + ((e - s) & ~7);
    for (; j < lim8; j += 8) {
        int ee[8]; uint4 v[8];
        #pragma unroll
        for (int u = 0; u < 8; u++) ee[u] = g_adj_n[j + u];
        #pragma unroll
        for (int u = 0; u < 8; u++)
            v[u] = *(const uint4*)&g_S2h[(size_t)ee[u] * DIM + lane * 8];
        #pragma unroll
        for (int u = 0; u < 8; u++) acc8(a, v[u], 1.0f);
    }
    for (; j < e; j++) {
        int e0 = g_adj_n[j];
        uint4 v0 = *(const uint4*)&g_S2h[(size_t)e0 * DIM + lane * 8];
        acc8(a, v0, 1.0f);
    }
    float dv = g_dv[w];
    float4 o0, o1;
    o0.x = a[0] * dv; o0.y = a[1] * dv; o0.z = a[2] * dv; o0.w = a[3] * dv;
    o1.x = a[4] * dv; o1.y = a[5] * dv; o1.z = a[6] * dv; o1.w = a[7] * dv;
    float* dst = out_g + (size_t)w * DIM + lane * 8;
    *(float4*)dst = o0;
    *(float4*)(dst + 4) = o1;
}

// ---------------- launch: e-side-first CSR, v-side hidden on side stream -----
extern "C" void kernel_launch(void* const* d_in, const int* in_sizes, int n_in,
                              void* d_out, int out_size) {
    const float* X  = (const float*)d_in[0];
    const void*  ni = d_in[1];
    const void*  ei = d_in[2];
    const float* W  = (const float*)d_in[3];
    const float* b  = (const float*)d_in[4];
    float* out = (float*)d_out;

    static cudaStream_t sB = nullptr, sC = nullptr;
    static cudaEvent_t evRoot = nullptr, evB = nullptr, evCntE = nullptr,
                       evScanE = nullptr, evSV = nullptr, evC = nullptr;
    if (sB == nullptr) {
        cudaStreamCreateWithFlags(&sB, cudaStreamNonBlocking);
        cudaStreamCreateWithFlags(&sC, cudaStreamNonBlocking);
        cudaEventCreateWithFlags(&evRoot, cudaEventDisableTiming);
        cudaEventCreateWithFlags(&evB, cudaEventDisableTiming);
        cudaEventCreateWithFlags(&evCntE, cudaEventDisableTiming);
        cudaEventCreateWithFlags(&evScanE, cudaEventDisableTiming);
        cudaEventCreateWithFlags(&evSV, cudaEventDisableTiming);
        cudaEventCreateWithFlags(&evC, cudaEventDisableTiming);
    }

    // fork: sB branches off the main (capture) stream at the root
    cudaEventRecord(evRoot, 0);
    cudaStreamWaitEvent(sB, evRoot, 0);

    // ---- chain B (sB): W transpose/round + tf32 GEMM ----
    convert_w_kernel<<<DIM, DIM, 0, sB>>>(W);
    dim3 ggrid(N_PAD / 128, DIM / 128);
    gemm_tf32_kernel<<<ggrid, 256, 0, sB>>>(X, b);
    cudaEventRecord(evB, sB);

    // ---- chain A (main): detect -> count_e -> scanE -> fill_e (edge side) ---
    detect_kernel<<<1, 32>>>(ni);
    count_e_kernel<<<(NNZ + 255) / 256, 256>>>(ei);
    cudaEventRecord(evCntE, 0);
    scan_p1_kernel<<<CH_E, 1024>>>(0);
    scan_p2_kernel<<<1, 64>>>(0);
    scan_p3_kernel<<<CH_E, 1024>>>(0);
    cudaEventRecord(evScanE, 0);
    fill_e_kernel<<<(NNZ / 4 + 255) / 256, 256>>>(ni, ei);

    // ---- chain C (sC): v-side, sequenced after count_e (NOT concurrent) -----
    cudaStreamWaitEvent(sC, evCntE, 0);
    count_v_kernel<<<(NNZ + 255) / 256, 256, 0, sC>>>(ni);
    scan_p1_kernel<<<CH_N, 1024, 0, sC>>>(1);
    cudaEventRecord(evSV, sC);                    // g_dv ready (EG needs it)
    scan_p2_kernel<<<1, 64, 0, sC>>>(1);
    scan_p3_kernel<<<CH_N, 1024, 0, sC>>>(1);
    fill_n_kernel<<<(NNZ / 4 + 255) / 256, 256, 0, sC>>>(ni, ei);
    cudaStreamWaitEvent(sC, evScanE, 0);          // deg_e consumed before zero
    zero_kernel<<<(N_NODES + 255) / 256, 256, 0, sC>>>();
    cudaEventRecord(evC, sC);

    // join GEMM + d_v, then edge gather
    cudaStreamWaitEvent(0, evB, 0);
    cudaStreamWaitEvent(0, evSV, 0);
    edge_gather_kernel<<<(N_EDGES * 32 + 255) / 256, 256>>>();

    // join chain C (adj_n, zero), then node gather
    cudaStreamWaitEvent(0, evC, 0);
    node_gather_kernel<<<(N_NODES * 32 + 255) / 256, 256>>>(out);
}